// round 5
// baseline (speedup 1.0000x reference)
#include <cuda_runtime.h>
#include <cuda_bf16.h>

#define Bc 256
#define Sc 512
#define Tc 128

// scratch (no allocations allowed; __device__ globals are the sanctioned path)
__device__ float g_Mexp[Tc * Tc];
__device__ float g_logZ[Bc];
__device__ float g_gold[Bc];

// ---------------------------------------------------------------------------
// Kernel 0: M = exp(transitions), precise expf (one-time, 16K elements)
// ---------------------------------------------------------------------------
__global__ void expm_kernel(const float* __restrict__ trans) {
    int i = blockIdx.x * blockDim.x + threadIdx.x;
    if (i < Tc * Tc) g_Mexp[i] = expf(trans[i]);
}

// ---------------------------------------------------------------------------
// Kernel 1: gold score per batch. Tags dtype (int32 vs int64) is sniffed
// device-side: int64 tags in [0,128) have ALL odd 32-bit words == 0;
// int32 tags have nonzero odd words w.p. 1 - 128^-512. Indices masked &127.
// ---------------------------------------------------------------------------
__global__ void gold_kernel(const float* __restrict__ em,
                            const unsigned int* __restrict__ tagsw,
                            const float* __restrict__ trans) {
    int b   = blockIdx.x;
    int tid = threadIdx.x;  // 128 threads

    // dtype sniff on the first 1024 words (same for every block; L2-hot)
    unsigned int odd_nonzero = 0;
    #pragma unroll
    for (int k = 0; k < 4; ++k) odd_nonzero |= tagsw[2 * (tid + 128 * k) + 1];
    int is32 = __syncthreads_or((int)(odd_nonzero != 0u));

    const unsigned int* tg = tagsw + (size_t)b * Sc * (is32 ? 1 : 2);
    int stride = is32 ? 1 : 2;
    const float* eb = em + (size_t)b * Sc * Tc;

    float acc = 0.f;
    for (int s = tid; s < Sc; s += 128) {
        int cur = (int)(tg[stride * s] & 127u);
        acc += eb[s * Tc + cur];
        if (s < Sc - 1) {
            int nxt = (int)(tg[stride * (s + 1)] & 127u);
            acc += trans[cur * Tc + nxt];
        }
    }
    #pragma unroll
    for (int o = 16; o; o >>= 1) acc += __shfl_xor_sync(0xffffffffu, acc, o);

    __shared__ float red[4];
    if ((tid & 31) == 0) red[tid >> 5] = acc;
    __syncthreads();
    if (tid == 0) g_gold[b] = (red[0] + red[1]) + (red[2] + red[3]);
}

// ---------------------------------------------------------------------------
// Kernel 2: forward recursion in linear domain.
// grid = 128 CTAs, block = 256 threads. CTA handles batch rows 2b, 2b+1.
// Thread (r, j): r = tid>>7 selects row, j = tid&127 selects output tag.
// M column j lives in 128 registers per thread (fully unrolled).
// ---------------------------------------------------------------------------
__global__ void __launch_bounds__(256, 1)
forward_kernel(const float* __restrict__ em) {
    __shared__ float4 alphaS[2][2][Tc / 4];   // [buf][row][tag/4]
    __shared__ float  red[2][4];

    int tid  = threadIdx.x;
    int r    = tid >> 7;
    int j    = tid & 127;
    int lane = tid & 31;
    int wir  = (tid >> 5) & 3;          // warp index within its row group
    int b    = blockIdx.x * 2 + r;
    const float* eb = em + (size_t)b * Sc * Tc;

    // --- load M column j into registers (coalesced across warp) ---
    float Mr[Tc];
    #pragma unroll
    for (int i = 0; i < Tc; ++i) Mr[i] = g_Mexp[i * Tc + j];

    // --- alpha_0 = exp(e_0) ---
    ((float*)alphaS[0][r])[j] = __expf(eb[j]);
    float carry  = 0.f;
    float evNext = eb[Tc + j];          // prefetch e_1
    __syncthreads();

    int buf = 0;
    for (int t = 1; t < Sc; ++t) {
        float ev = evNext;
        if (t + 1 < Sc) evNext = eb[(t + 1) * Tc + j];  // hide DRAM behind FMA block

        const float4* aS = alphaS[buf][r];
        float a0 = 0.f, a1 = 0.f, a2 = 0.f, a3 = 0.f;
        #pragma unroll
        for (int q = 0; q < Tc / 4; ++q) {
            float4 av = aS[q];
            a0 += av.x * Mr[4 * q];
            a1 += av.y * Mr[4 * q + 1];
            a2 += av.z * Mr[4 * q + 2];
            a3 += av.w * Mr[4 * q + 3];
        }
        float val = ((a0 + a1) + (a2 + a3)) * __expf(ev);

        if ((t & 3) == 0 || t == Sc - 1) {
            // row-sum rescale: keep fp32 in range, fold scale into carry
            float s = val;
            #pragma unroll
            for (int o = 16; o; o >>= 1) s += __shfl_xor_sync(0xffffffffu, s, o);
            if (lane == 0) red[r][wir] = s;
            __syncthreads();
            float total = (red[r][0] + red[r][1]) + (red[r][2] + red[r][3]);
            carry += __logf(total);
            val *= (1.f / total);
        }

        ((float*)alphaS[buf ^ 1][r])[j] = val;
        buf ^= 1;
        __syncthreads();
    }

    // last step (t=511) was a rescale step -> sum(normalized)=1 -> logZ = carry
    if (j == 0) g_logZ[b] = carry;
}

// ---------------------------------------------------------------------------
// Kernel 3: out = mean(logZ - gold)
// ---------------------------------------------------------------------------
__global__ void finalize_kernel(float* __restrict__ out) {
    int tid  = threadIdx.x;  // 256
    int lane = tid & 31;
    float v  = g_logZ[tid] - g_gold[tid];
    #pragma unroll
    for (int o = 16; o; o >>= 1) v += __shfl_xor_sync(0xffffffffu, v, o);

    __shared__ float red[8];
    if (lane == 0) red[tid >> 5] = v;
    __syncthreads();
    if (tid == 0) {
        float s = 0.f;
        #pragma unroll
        for (int w = 0; w < 8; ++w) s += red[w];
        out[0] = s * (1.f / (float)Bc);
    }
}

// ---------------------------------------------------------------------------
// Inputs bound BY ELEMENT COUNT (order-independent):
//   16,777,216 -> emissions ; 131,072 -> tags ; 16,384 -> transitions
// ---------------------------------------------------------------------------
extern "C" void kernel_launch(void* const* d_in, const int* in_sizes, int n_in,
                              void* d_out, int out_size) {
    const float*        em    = nullptr;
    const unsigned int* tagsw = nullptr;
    const float*        trans = nullptr;

    for (int i = 0; i < n_in; ++i) {
        if (in_sizes[i] == Bc * Sc * Tc)      em    = (const float*)d_in[i];
        else if (in_sizes[i] == Bc * Sc)      tagsw = (const unsigned int*)d_in[i];
        else if (in_sizes[i] == Tc * Tc)      trans = (const float*)d_in[i];
    }
    float* out = (float*)d_out;

    expm_kernel<<<16, 1024>>>(trans);
    gold_kernel<<<Bc, 128>>>(em, tagsw, trans);
    forward_kernel<<<Bc / 2, 256>>>(em);
    finalize_kernel<<<1, 256>>>(out);
}